// round 6
// baseline (speedup 1.0000x reference)
#include <cuda_runtime.h>
#include <cuda_bf16.h>
#include <math.h>

#define BSN 32
#define QN 1024
#define KN 96
#define QN1 (QN + 1)
#define INFV 1000000000.0f
#define NELEM (QN * 3)   // 98304 per input

__device__ __forceinline__ bool probe_is_labels(const float* x) {
    const int qs[6] = {0, 13, 95, 96, 511, 1023};
    #pragma unroll
    for (int t = 0; t < 6; t++) {
        float v = x[qs[t] * 3];
        if (v != 0.0f && v != 1.0f) return false;
    }
    return true;
}

// Bit-exact replica of XLA:CPU GenerateVF32Exp (llvm_ir_runtime.cc).
// Cephes-style: clamp, fx = floor(fma(x, log2e, 0.5)), TWO-STEP reduction with
// separate mul/sub (must NOT be fma-contracted), Horner via fma, 2^fx by bit
// construction, final max(y*scale, input). All ops pinned with _rn intrinsics.
__device__ __forceinline__ float xla_cpu_expf(float x_in) {
    float x = fmaxf(fminf(x_in, 88.3762626647950f), -88.3762626647949f);
    float fx = floorf(__fmaf_rn(x, 1.44269504088896341f, 0.5f));
    float tmp = __fmul_rn(0.693359375f, fx);
    float z   = __fmul_rn(-2.12194440e-4f, fx);
    x = __fsub_rn(x, tmp);
    x = __fsub_rn(x, z);
    float x2 = __fmul_rn(x, x);
    float y = __fmaf_rn(x, 1.9875691500E-4f, 1.3981999507E-3f);
    y = __fmaf_rn(y, x, 8.3334519073E-3f);
    y = __fmaf_rn(y, x, 4.1665795894E-2f);
    y = __fmaf_rn(y, x, 1.6666665459E-1f);
    y = __fmaf_rn(y, x, 5.0000001201E-1f);
    y = __fmaf_rn(y, x2, x);
    y = __fadd_rn(y, 1.0f);
    int k = (int)fx;                         // FPToSI, fx integral
    float scale = __int_as_float((k + 127) << 23);
    return fmaxf(__fmul_rn(y, scale), x_in);
}

// XLA logistic expander: logistic(x) = 1 / (1 + exp(-x)), exact div/add.
__device__ __forceinline__ float xla_sigmoid(float x) {
    float e = xla_cpu_expf(-x);
    return __fdiv_rn(1.0f, __fadd_rn(1.0f, e));
}

__global__ __launch_bounds__(1024, 1)
void hungarian_kernel(const float* __restrict__ in0,
                      const float* __restrict__ in1,
                      float* __restrict__ out,
                      int write_col_ind) {
    __shared__ float v[QN1];
    __shared__ float minv[QN1];
    __shared__ int   way[QN1];
    __shared__ int   p[QN1];
    __shared__ float u[KN + 1];
    __shared__ float t1[KN];
    __shared__ float t2[KN];
    __shared__ float redv[32];
    __shared__ int   redi[32];
    __shared__ int   a[KN];
    __shared__ int   swap_flag;

    const int b    = blockIdx.x;
    const int tid  = threadIdx.x;
    const int j    = tid + 1;              // this thread's column, 1..1024
    const int lane = tid & 31;
    const int wid  = tid >> 5;

    if (tid == 0) {
        bool l0 = probe_is_labels(in0);
        bool l1 = probe_is_labels(in1);
        swap_flag = (l0 && !l1) ? 1 : 0;
    }
    __syncthreads();
    const float* L  = (swap_flag ? in1 : in0) + (size_t)b * NELEM;  // logits
    const float* Lb = (swap_flag ? in0 : in1) + (size_t)b * NELEM;  // labels

    // Per-thread column data (q = tid)
    float x0 = L[tid * 3 + 0];
    float negprob = -xla_sigmoid(x0);
    float b1 = L[tid * 3 + 1];
    float b2 = L[tid * 3 + 2];

    // Init shared state
    if (tid < KN) {
        t1[tid] = Lb[tid * 3 + 1];
        t2[tid] = Lb[tid * 3 + 2];
        u[tid + 1] = 0.0f;
    }
    v[j] = 0.0f;
    p[j] = 0;
    if (tid == 0) { u[0] = 0.0f; v[0] = 0.0f; p[0] = 0; }
    __syncthreads();

    for (int i = 1; i <= KN; i++) {
        minv[j] = INFV;
        way[j]  = 0;
        if (tid == 0) { p[0] = i; minv[0] = INFV; way[0] = 0; }
        __syncthreads();

        int j0 = 0;
        bool meUsed = false;
        while (true) {
            if (j == j0) meUsed = true;
            int   i0  = p[j0];
            float ui0 = u[i0];
            int   k   = i0 - 1;
            float tt1 = t1[k];
            float tt2 = t2[k];

            float cand;
            int   candj = j;
            if (!meUsed) {
                float c   = negprob + (fabsf(b1 - tt1) + fabsf(b2 - tt2));
                float cur = (c - ui0) - v[j];
                float mj  = minv[j];
                if (cur < mj) { mj = cur; minv[j] = cur; way[j] = j0; }
                cand = mj;
            } else {
                cand = INFV;
            }

            // argmin with first-index tie-break (matches jnp.argmin)
            #pragma unroll
            for (int off = 16; off; off >>= 1) {
                float ov = __shfl_down_sync(0xffffffffu, cand, off);
                int   oi = __shfl_down_sync(0xffffffffu, candj, off);
                if (ov < cand || (ov == cand && oi < candj)) { cand = ov; candj = oi; }
            }
            if (lane == 0) { redv[wid] = cand; redi[wid] = candj; }
            __syncthreads();
            if (wid == 0) {
                cand  = redv[lane];
                candj = redi[lane];
                #pragma unroll
                for (int off = 16; off; off >>= 1) {
                    float ov = __shfl_down_sync(0xffffffffu, cand, off);
                    int   oi = __shfl_down_sync(0xffffffffu, candj, off);
                    if (ov < cand || (ov == cand && oi < candj)) { cand = ov; candj = oi; }
                }
                if (lane == 0) { redv[0] = cand; redi[0] = candj; }
            }
            __syncthreads();
            float delta = redv[0];
            int   j1    = redi[0];

            if (!meUsed) {
                minv[j] -= delta;
            } else {
                v[j] -= delta;
                u[p[j]] += delta;   // distinct rows across used columns: race-free
            }
            if (tid == 0) u[p[0]] += delta;   // column 0 is always "used"

            j0 = j1;
            __syncthreads();
            if (p[j0] == 0) break;   // reached a free column
        }

        // augment along the alternating path
        if (tid == 0) {
            int jj = j0;
            while (jj != 0) {
                int jn = way[jj];
                p[jj] = p[jn];
                jj = jn;
            }
        }
        __syncthreads();
    }

    // Extract assignment: a[row] = column
    if (p[j] > 0) a[p[j] - 1] = j - 1;
    __syncthreads();

    // row_ind = sort(a), col_ind = argsort(a); values distinct; output is f32
    if (tid < KN) {
        int av = a[tid];
        int rank = 0;
        #pragma unroll 8
        for (int m = 0; m < KN; m++) rank += (a[m] < av);
        out[b * KN + rank] = (float)av;                                  // row_ind
        if (write_col_ind) out[BSN * KN + b * KN + rank] = (float)tid;   // col_ind
    }
}

extern "C" void kernel_launch(void* const* d_in, const int* in_sizes, int n_in,
                              void* d_out, int out_size) {
    const float* in0;
    const float* in1;
    if (n_in == 1) {
        in0 = (const float*)d_in[0];
        in1 = in0 + NELEM * BSN;
    } else {
        int i0 = -1, i1 = -1;
        for (int t = 0; t < n_in; t++) {
            if (in_sizes[t] == BSN * NELEM) {
                if (i0 < 0) i0 = t;
                else if (i1 < 0) i1 = t;
            }
        }
        if (i0 < 0) { i0 = 0; i1 = 1; }
        if (i1 < 0) i1 = (i0 == 0 ? 1 : 0);
        in0 = (const float*)d_in[i0];
        in1 = (const float*)d_in[i1];
    }
    float* out = (float*)d_out;
    int write_col = (out_size >= 2 * BSN * KN) ? 1 : 0;
    hungarian_kernel<<<BSN, 1024>>>(in0, in1, out, write_col);
}

// round 7
// speedup vs baseline: 1.8887x; 1.8887x over previous
#include <cuda_runtime.h>
#include <cuda_bf16.h>
#include <math.h>

#define BSN 32
#define QN 1024
#define KN 96
#define QN1 (QN + 1)
#define INFV 1000000000.0f
#define NELEM (QN * 3)   // 98304 per input
#define NT 256
#define CPT 4
#define NW (NT / 32)

__device__ __forceinline__ bool probe_is_labels(const float* x) {
    const int qs[6] = {0, 13, 95, 96, 511, 1023};
    #pragma unroll
    for (int t = 0; t < 6; t++) {
        float v = x[qs[t] * 3];
        if (v != 0.0f && v != 1.0f) return false;
    }
    return true;
}

// Bit-exact replica of XLA:CPU GenerateVF32Exp (proven in R6).
__device__ __forceinline__ float xla_cpu_expf(float x_in) {
    float x = fmaxf(fminf(x_in, 88.3762626647950f), -88.3762626647949f);
    float fx = floorf(__fmaf_rn(x, 1.44269504088896341f, 0.5f));
    float tmp = __fmul_rn(0.693359375f, fx);
    float z   = __fmul_rn(-2.12194440e-4f, fx);
    x = __fsub_rn(x, tmp);
    x = __fsub_rn(x, z);
    float x2 = __fmul_rn(x, x);
    float y = __fmaf_rn(x, 1.9875691500E-4f, 1.3981999507E-3f);
    y = __fmaf_rn(y, x, 8.3334519073E-3f);
    y = __fmaf_rn(y, x, 4.1665795894E-2f);
    y = __fmaf_rn(y, x, 1.6666665459E-1f);
    y = __fmaf_rn(y, x, 5.0000001201E-1f);
    y = __fmaf_rn(y, x2, x);
    y = __fadd_rn(y, 1.0f);
    int k = (int)fx;
    float scale = __int_as_float((k + 127) << 23);
    return fmaxf(__fmul_rn(y, scale), x_in);
}

__device__ __forceinline__ float xla_sigmoid(float x) {
    float e = xla_cpu_expf(-x);
    return __fdiv_rn(1.0f, __fadd_rn(1.0f, e));
}

// monotone float -> u32 map (no NaNs / no -0.0 in our domain, proven)
__device__ __forceinline__ unsigned int fmap(float f) {
    unsigned int u = __float_as_uint(f);
    return (u & 0x80000000u) ? ~u : (u | 0x80000000u);
}
__device__ __forceinline__ float funmap(unsigned int m) {
    unsigned int u = (m & 0x80000000u) ? (m & 0x7FFFFFFFu) : ~m;
    return __uint_as_float(u);
}

__global__ __launch_bounds__(NT, 1)
void hungarian_kernel(const float* __restrict__ in0,
                      const float* __restrict__ in1,
                      float* __restrict__ out,
                      int write_col_ind) {
    __shared__ float u_sh[KN + 1];
    __shared__ int   p_sh[QN1];
    __shared__ int   way_sh[QN1];
    __shared__ float t1_sh[KN], t2_sh[KN];
    __shared__ unsigned long long redk[2][NW];
    __shared__ int   a_sh[KN];
    __shared__ int   swap_flag;

    const int tid  = threadIdx.x;
    const int b    = blockIdx.x;
    const int lane = tid & 31;
    const int wid  = tid >> 5;

    if (tid == 0) {
        bool l0 = probe_is_labels(in0);
        bool l1 = probe_is_labels(in1);
        swap_flag = (l0 && !l1) ? 1 : 0;
    }
    __syncthreads();
    const float* L  = (swap_flag ? in1 : in0) + (size_t)b * NELEM;  // logits
    const float* Lb = (swap_flag ? in0 : in1) + (size_t)b * NELEM;  // labels

    // Per-thread column data: columns jc = tid*4 + c + 1 (contiguous => lane
    // order == j order, required for the ballot tie-break).
    float negprob[CPT], b1r[CPT], b2r[CPT], vr[CPT], minv[CPT], uacc[CPT];
    int   rowc[CPT];
    #pragma unroll
    for (int c = 0; c < CPT; c++) {
        int q = tid * CPT + c;
        negprob[c] = -xla_sigmoid(L[q * 3 + 0]);
        b1r[c] = L[q * 3 + 1];
        b2r[c] = L[q * 3 + 2];
        vr[c]  = 0.0f;
    }
    if (tid < KN) {
        t1_sh[tid] = Lb[tid * 3 + 1];
        t2_sh[tid] = Lb[tid * 3 + 2];
        u_sh[tid + 1] = 0.0f;
    }
    if (tid == 0) u_sh[0] = 0.0f;
    for (int idx = tid; idx < QN1; idx += NT) p_sh[idx] = 0;
    __syncthreads();

    float u0acc = 0.0f;

    for (int i = 1; i <= KN; i++) {
        #pragma unroll
        for (int c = 0; c < CPT; c++) minv[c] = INFV;
        unsigned int usedm = 0;
        int   j0  = 0;
        int   i0  = i;
        float ui0 = u_sh[i0];
        float tt1 = t1_sh[i0 - 1], tt2 = t2_sh[i0 - 1];
        if (tid == 0) u0acc = ui0;
        int par = 0;

        while (true) {
            // mark used (j0 owner)
            #pragma unroll
            for (int c = 0; c < CPT; c++) {
                int jc = tid * CPT + c + 1;
                if (jc == j0) { usedm |= (1u << c); uacc[c] = ui0; rowc[c] = i0; }
            }
            // compute candidates + local argmin (ascending j, strict <)
            unsigned long long best = 0xFFFFFFFFFFFFFFFFull;
            #pragma unroll
            for (int c = 0; c < CPT; c++) {
                if (!(usedm & (1u << c))) {
                    int jc = tid * CPT + c + 1;
                    float bbox = fabsf(b1r[c] - tt1) + fabsf(b2r[c] - tt2);
                    float cur  = ((negprob[c] + bbox) - ui0) - vr[c];
                    if (cur < minv[c]) { minv[c] = cur; way_sh[jc] = j0; }
                    unsigned long long key =
                        ((unsigned long long)fmap(minv[c]) << 32) | (unsigned int)jc;
                    if (key < best) best = key;
                }
            }
            // warp argmin: redux on mapped value, lowest-lane tie-break (= lowest j)
            unsigned int mval = (unsigned int)(best >> 32);
            unsigned int wmin;
            asm("redux.sync.min.u32 %0, %1, 0xffffffff;" : "=r"(wmin) : "r"(mval));
            unsigned int ball = __ballot_sync(0xffffffffu, mval == wmin);
            int src = __ffs(ball) - 1;
            unsigned long long wkey = __shfl_sync(0xffffffffu, best, src);
            if (lane == 0) redk[par][wid] = wkey;
            __syncthreads();
            // cross-warp min: every thread redundantly (no 2nd barrier needed)
            unsigned long long g = redk[par][0];
            #pragma unroll
            for (int w = 1; w < NW; w++) {
                unsigned long long kk = redk[par][w];
                if (kk < g) g = kk;
            }
            float delta = funmap((unsigned int)(g >> 32));
            int   j1    = (int)(unsigned int)g;
            int   i0n   = p_sh[j1];      // p constant during path
            // updates (sequential per-step adds: bit-exact vs JAX)
            #pragma unroll
            for (int c = 0; c < CPT; c++) {
                if (usedm & (1u << c)) { uacc[c] += delta; vr[c] -= delta; }
                else                   { minv[c] -= delta; }
            }
            if (tid == 0) u0acc += delta;
            j0 = j1;
            i0 = i0n;
            if (i0 == 0) break;          // reached a free column
            ui0 = u_sh[i0];
            tt1 = t1_sh[i0 - 1]; tt2 = t2_sh[i0 - 1];
            par ^= 1;
        }

        // flush u (store, not add: register held the exact sequential value)
        #pragma unroll
        for (int c = 0; c < CPT; c++)
            if (usedm & (1u << c)) u_sh[rowc[c]] = uacc[c];
        if (tid == 0) u_sh[i] = u0acc;
        __syncthreads();

        if (tid == 0) {       // augment along alternating path
            int jj = j0;
            while (jj != 0) {
                int jn = way_sh[jj];
                p_sh[jj] = (jn == 0) ? i : p_sh[jn];
                jj = jn;
            }
        }
        __syncthreads();
    }

    // a[row] = column
    #pragma unroll
    for (int c = 0; c < CPT; c++) {
        int jc = tid * CPT + c + 1;
        int pv = p_sh[jc];
        if (pv > 0) a_sh[pv - 1] = jc - 1;
    }
    __syncthreads();

    // row_ind = sort(a), col_ind = argsort(a); output f32
    if (tid < KN) {
        int av = a_sh[tid];
        int rank = 0;
        #pragma unroll 8
        for (int m = 0; m < KN; m++) rank += (a_sh[m] < av);
        out[b * KN + rank] = (float)av;
        if (write_col_ind) out[BSN * KN + b * KN + rank] = (float)tid;
    }
}

extern "C" void kernel_launch(void* const* d_in, const int* in_sizes, int n_in,
                              void* d_out, int out_size) {
    const float* in0;
    const float* in1;
    if (n_in == 1) {
        in0 = (const float*)d_in[0];
        in1 = in0 + NELEM * BSN;
    } else {
        int i0 = -1, i1 = -1;
        for (int t = 0; t < n_in; t++) {
            if (in_sizes[t] == BSN * NELEM) {
                if (i0 < 0) i0 = t;
                else if (i1 < 0) i1 = t;
            }
        }
        if (i0 < 0) { i0 = 0; i1 = 1; }
        if (i1 < 0) i1 = (i0 == 0 ? 1 : 0);
        in0 = (const float*)d_in[i0];
        in1 = (const float*)d_in[i1];
    }
    float* out = (float*)d_out;
    int write_col = (out_size >= 2 * BSN * KN) ? 1 : 0;
    hungarian_kernel<<<BSN, NT>>>(in0, in1, out, write_col);
}

// round 9
// speedup vs baseline: 2.5290x; 1.3391x over previous
#include <cuda_runtime.h>
#include <cuda_bf16.h>
#include <math.h>

#define BSN 32
#define QN 1024
#define KN 96
#define QN1 (QN + 1)
#define INFV 1000000000.0f
#define NELEM (QN * 3)   // 98304 per input
#define NT 128
#define CPT 8
#define NW (NT / 32)
#define FINF __int_as_float(0x7F800000)

__device__ __forceinline__ bool probe_is_labels(const float* x) {
    const int qs[6] = {0, 13, 95, 96, 511, 1023};
    #pragma unroll
    for (int t = 0; t < 6; t++) {
        float v = x[qs[t] * 3];
        if (v != 0.0f && v != 1.0f) return false;
    }
    return true;
}

// Bit-exact replica of XLA:CPU GenerateVF32Exp (proven R6).
__device__ __forceinline__ float xla_cpu_expf(float x_in) {
    float x = fmaxf(fminf(x_in, 88.3762626647950f), -88.3762626647949f);
    float fx = floorf(__fmaf_rn(x, 1.44269504088896341f, 0.5f));
    float tmp = __fmul_rn(0.693359375f, fx);
    float z   = __fmul_rn(-2.12194440e-4f, fx);
    x = __fsub_rn(x, tmp);
    x = __fsub_rn(x, z);
    float x2 = __fmul_rn(x, x);
    float y = __fmaf_rn(x, 1.9875691500E-4f, 1.3981999507E-3f);
    y = __fmaf_rn(y, x, 8.3334519073E-3f);
    y = __fmaf_rn(y, x, 4.1665795894E-2f);
    y = __fmaf_rn(y, x, 1.6666665459E-1f);
    y = __fmaf_rn(y, x, 5.0000001201E-1f);
    y = __fmaf_rn(y, x2, x);
    y = __fadd_rn(y, 1.0f);
    int k = (int)fx;
    float scale = __int_as_float((k + 127) << 23);
    return fmaxf(__fmul_rn(y, scale), x_in);
}

__device__ __forceinline__ float xla_sigmoid(float x) {
    float e = xla_cpu_expf(-x);
    return __fdiv_rn(1.0f, __fadd_rn(1.0f, e));
}

// monotone float -> u32 map (no NaN / -0.0 in our domain)
__device__ __forceinline__ unsigned int fmap(float f) {
    unsigned int u = __float_as_uint(f);
    return (u & 0x80000000u) ? ~u : (u | 0x80000000u);
}
__device__ __forceinline__ float funmap(unsigned int m) {
    unsigned int u = (m & 0x80000000u) ? (m & 0x7FFFFFFFu) : ~m;
    return __uint_as_float(u);
}

__device__ __forceinline__ unsigned int redux_min_u32(unsigned int x) {
    unsigned int r;
    asm("redux.sync.min.u32 %0, %1, 0xffffffff;" : "=r"(r) : "r"(x));
    return r;
}

__global__ __launch_bounds__(NT, 1)
void hungarian_kernel(const float* __restrict__ in0,
                      const float* __restrict__ in1,
                      float* __restrict__ out,
                      int write_col_ind) {
    __shared__ float  u_sh[KN + 1];
    __shared__ int    p_sh[QN1];
    __shared__ int    way_sh[QN1];
    __shared__ float  t1_sh[KN], t2_sh[KN];
    __shared__ float4 prow[QN1];            // {p (int bits), u[p], t1[p-1], t2[p-1]}
    __shared__ unsigned long long redk[2][NW];
    __shared__ int    a_sh[KN];
    __shared__ int    swap_flag;

    const int tid  = threadIdx.x;
    const int b    = blockIdx.x;
    const int lane = tid & 31;
    const int wid  = tid >> 5;

    if (tid == 0) {
        bool l0 = probe_is_labels(in0);
        bool l1 = probe_is_labels(in1);
        swap_flag = (l0 && !l1) ? 1 : 0;
    }
    __syncthreads();
    const float* L  = (swap_flag ? in1 : in0) + (size_t)b * NELEM;  // logits
    const float* Lb = (swap_flag ? in0 : in1) + (size_t)b * NELEM;  // labels

    // Per-thread columns: jc = tid*CPT + c + 1 (contiguous)
    float negorig[CPT], np[CPT], b1r[CPT], b2r[CPT], vr[CPT], minv[CPT], uacc[CPT];
    int   rowc[CPT];
    #pragma unroll
    for (int c = 0; c < CPT; c++) {
        int q = tid * CPT + c;
        negorig[c] = -xla_sigmoid(L[q * 3 + 0]);
        b1r[c] = L[q * 3 + 1];
        b2r[c] = L[q * 3 + 2];
        vr[c]  = 0.0f;
    }
    if (tid < KN) {
        t1_sh[tid] = Lb[tid * 3 + 1];
        t2_sh[tid] = Lb[tid * 3 + 2];
        u_sh[tid + 1] = 0.0f;
    }
    if (tid == 0) u_sh[0] = 0.0f;
    for (int idx = tid; idx < QN1; idx += NT) p_sh[idx] = 0;
    __syncthreads();

    for (int i = 1; i <= KN; i++) {
        // rebuild prow: p and u are frozen during a path (proven R7)
        for (int idx = tid; idx < QN; idx += NT) {
            int jj = idx + 1;
            int pi = p_sh[jj];
            float4 r;
            r.x = __int_as_float(pi);
            if (pi > 0) { r.y = u_sh[pi]; r.z = t1_sh[pi - 1]; r.w = t2_sh[pi - 1]; }
            else        { r.y = 0.0f; r.z = 0.0f; r.w = 0.0f; }
            prow[jj] = r;
        }

        #pragma unroll
        for (int c = 0; c < CPT; c++) { minv[c] = INFV; np[c] = negorig[c]; }
        float bestv = INFV;
        unsigned int usedm = 0;
        int   j0 = 0, i0 = i;
        float ui0 = u_sh[i];
        float tt1 = t1_sh[i - 1], tt2 = t2_sh[i - 1];
        float u0acc = ui0;     // column 0 (always used), tracked by tid 0
        int par = 0;

        while (true) {
            // mark used: owner poisons the WORKING copy (np/minv = +Inf), rescans bestv
            unsigned int t = (unsigned int)(j0 - 1 - tid * CPT);
            if (t < CPT) {
                usedm |= (1u << t);
                #pragma unroll
                for (int c = 0; c < CPT; c++)
                    if (c == (int)t) {
                        np[c] = FINF; minv[c] = FINF;
                        uacc[c] = ui0; rowc[c] = i0;
                    }
                bestv = minv[0];
                #pragma unroll
                for (int c = 1; c < CPT; c++) bestv = fminf(bestv, minv[c]);
            }

            // compute candidates (no predicates; used cols give cur = +Inf)
            #pragma unroll
            for (int c = 0; c < CPT; c++) {
                float d1 = b1r[c] - tt1;
                float d2 = b2r[c] - tt2;
                float s  = fabsf(d1) + fabsf(d2);
                float cur = ((np[c] + s) - ui0) - vr[c];
                if (cur < minv[c]) way_sh[tid * CPT + c + 1] = j0;
                minv[c] = fminf(minv[c], cur);
                bestv   = fminf(bestv, cur);
            }

            // warp argmin: redux on mapped value, lazy j scan, redux on j
            unsigned int mb   = fmap(bestv);
            unsigned int wmin = redux_min_u32(mb);
            bool W = (mb == wmin);
            unsigned int jcand = 0x7FFFFFFFu;
            #pragma unroll
            for (int c = CPT - 1; c >= 0; c--)
                if (W && minv[c] == bestv) jcand = (unsigned int)(tid * CPT + c + 1);
            unsigned int jmin = redux_min_u32(jcand);
            if (lane == 0)
                redk[par][wid] = ((unsigned long long)wmin << 32) | jmin;
            __syncthreads();

            // cross-warp min (every thread, redundantly; no second barrier)
            unsigned long long g = redk[par][0];
            #pragma unroll
            for (int w = 1; w < NW; w++) {
                unsigned long long kk = redk[par][w];
                if (kk < g) g = kk;
            }
            float delta = funmap((unsigned int)(g >> 32));
            int   j1    = (int)(unsigned int)g;

            // updates (sequential per-step adds: bit-exact vs JAX; Inf stays Inf)
            #pragma unroll
            for (int c = 0; c < CPT; c++) {
                minv[c] -= delta;
                if (usedm & (1u << c)) { uacc[c] += delta; vr[c] -= delta; }
            }
            bestv -= delta;
            if (tid == 0) u0acc += delta;

            float4 pr = prow[j1];
            j0 = j1;
            i0 = __float_as_int(pr.x);
            if (i0 == 0) break;        // free column reached
            ui0 = pr.y; tt1 = pr.z; tt2 = pr.w;
            par ^= 1;
        }

        // flush u (stores of exactly-accumulated registers)
        #pragma unroll
        for (int c = 0; c < CPT; c++)
            if (usedm & (1u << c)) u_sh[rowc[c]] = uacc[c];
        if (tid == 0) u_sh[i] = u0acc;
        __syncthreads();

        if (tid == 0) {                 // augment
            int jj = j0;
            while (jj != 0) {
                int jn = way_sh[jj];
                p_sh[jj] = (jn == 0) ? i : p_sh[jn];
                jj = jn;
            }
        }
        __syncthreads();
    }

    // a[row] = column
    #pragma unroll
    for (int c = 0; c < CPT; c++) {
        int jc = tid * CPT + c + 1;
        int pv = p_sh[jc];
        if (pv > 0) a_sh[pv - 1] = jc - 1;
    }
    __syncthreads();

    // row_ind = sort(a), col_ind = argsort(a); output f32
    if (tid < KN) {
        int av = a_sh[tid];
        int rank = 0;
        #pragma unroll 8
        for (int m = 0; m < KN; m++) rank += (a_sh[m] < av);
        out[b * KN + rank] = (float)av;
        if (write_col_ind) out[BSN * KN + b * KN + rank] = (float)tid;
    }
}

extern "C" void kernel_launch(void* const* d_in, const int* in_sizes, int n_in,
                              void* d_out, int out_size) {
    const float* in0;
    const float* in1;
    if (n_in == 1) {
        in0 = (const float*)d_in[0];
        in1 = in0 + NELEM * BSN;
    } else {
        int i0 = -1, i1 = -1;
        for (int t = 0; t < n_in; t++) {
            if (in_sizes[t] == BSN * NELEM) {
                if (i0 < 0) i0 = t;
                else if (i1 < 0) i1 = t;
            }
        }
        if (i0 < 0) { i0 = 0; i1 = 1; }
        if (i1 < 0) i1 = (i0 == 0 ? 1 : 0);
        in0 = (const float*)d_in[i0];
        in1 = (const float*)d_in[i1];
    }
    float* out = (float*)d_out;
    int write_col = (out_size >= 2 * BSN * KN) ? 1 : 0;
    hungarian_kernel<<<BSN, NT>>>(in0, in1, out, write_col);
}